// round 8
// baseline (speedup 1.0000x reference)
#include <cuda_runtime.h>
#include <math.h>
#include <stdint.h>

#define Bx 4
#define Sx 128
#define Dx 256
#define Hx 8
#define NB 160            // persistent grid size (all co-resident)

static __device__ float g_V [Bx*Sx*Dx];      // V = x@Wv.T + bv
static __device__ float g_QK[Bx*Sx*64];      // raw Q/K projections (8h x (4q|4k))
static __device__ float g_AO[Bx*Sx*Dx];      // attention output (pre-Wo)

static __device__ unsigned g_count = 0;      // barrier arrivals
static __device__ unsigned g_gen   = 0;      // barrier generation (monotonic)

// ---------------------------------------------------------------------------
// Grid-wide barrier (persistent, one-wave). Generation-based: target is
// computed from the generation observed at launch start, so state carries
// across graph replays deterministically.
// ---------------------------------------------------------------------------
__device__ __forceinline__ void grid_bar(unsigned target)
{
    __threadfence();
    __syncthreads();
    if (threadIdx.x == 0) {
        unsigned old = atomicAdd(&g_count, 1u);
        if (old == NB - 1u) {
            atomicExch(&g_count, 0u);
            __threadfence();
            *(volatile unsigned*)&g_gen = target;
        } else {
            while (*(volatile unsigned*)&g_gen != target) { }
        }
    }
    __syncthreads();
    __threadfence();
}

// ---------------------------------------------------------------------------
// GEMM core (R5-proven): C[m0+m][n0+n] = sum_k A[m][k]*B[n][k] + bias[n].
// 32m x 32n, 256 thr. Warp w: n-group ng=w&3 (8 n), k4-parity kp=w>>2.
// Thread: m=lane, 8 n, split accumulators. As/Bs [32][33] f4 padded.
// qk mode: B rows / bias gathered from (Wq|Wk) by column map
//   col -> h=col>>3, side=(col>>2)&1, w=col&3, row = h*32+w.
// ---------------------------------------------------------------------------
__device__ void gemm32x32(
    const float4* __restrict__ A4,
    const float4* __restrict__ Bq4, const float4* __restrict__ Bk4,
    const float* __restrict__ biasq, const float* __restrict__ biask,
    float* __restrict__ C, int m0, int n0, int cstride, int qk, float* sm)
{
    float4* As = (float4*)sm;            // [32][33] float4
    float4* Bs = (float4*)sm + 32*33;    // [32][33] float4
    const int tid  = threadIdx.x;
    const int lane = tid & 31;
    const int w    = tid >> 5;
    const int ng   = w & 3;
    const int kp   = w >> 2;

    float acc[8][2];
#pragma unroll
    for (int j = 0; j < 8; j++) { acc[j][0] = 0.f; acc[j][1] = 0.f; }

    const float4* Ap = As + lane*33 + kp;
    const float4* Bp = Bs + (ng*8)*33 + kp;

    for (int kc = 0; kc < 2; kc++) {
#pragma unroll
        for (int t = 0; t < 4; t++) {
            const int idx = tid + (t << 8);
            const int r = idx >> 5, c = idx & 31;
            As[r*33 + c] = A4[(m0 + r)*64 + (kc << 5) + c];
            int brow;
            const float4* bp;
            if (qk) {
                const int col = n0 + r;
                brow = ((col >> 3)*32) + (col & 3);
                bp = ((col >> 2) & 1) ? Bk4 : Bq4;
            } else {
                brow = n0 + r;
                bp = Bq4;
            }
            Bs[r*33 + c] = bp[brow*64 + (kc << 5) + c];
        }
        __syncthreads();
#pragma unroll 4
        for (int k4 = 0; k4 < 16; k4++) {
            const float4 a = Ap[k4*2];
#pragma unroll
            for (int j = 0; j < 8; j++) {
                const float4 b = Bp[j*33 + k4*2];
                acc[j][0] = fmaf(a.x, b.x, acc[j][0]);
                acc[j][1] = fmaf(a.y, b.y, acc[j][1]);
                acc[j][0] = fmaf(a.z, b.z, acc[j][0]);
                acc[j][1] = fmaf(a.w, b.w, acc[j][1]);
            }
        }
        __syncthreads();
    }

    // cross-parity reduction through smem (17-pad: conflict-free)
    float* red = sm;
    if (kp == 1) {
#pragma unroll
        for (int j = 0; j < 8; j++) {
            red[(ng*32 + lane)*17 + j*2    ] = acc[j][0];
            red[(ng*32 + lane)*17 + j*2 + 1] = acc[j][1];
        }
    }
    __syncthreads();
    if (kp == 0) {
        const int n = n0 + ng*8;
        const float* rp = &red[(ng*32 + lane)*17];
        float o[8];
#pragma unroll
        for (int j = 0; j < 8; j++) {
            const int col = n + j;
            float bb;
            if (qk) {
                const int row = ((col >> 3)*32) + (col & 3);
                bb = (((col >> 2) & 1) ? biask : biasq)[row];
            } else {
                bb = biasq[col];
            }
            o[j] = acc[j][0] + acc[j][1] + rp[j*2] + rp[j*2 + 1] + bb;
        }
        float* cp = &C[(m0 + lane)*cstride + n];
        *(float4*)cp       = make_float4(o[0], o[1], o[2], o[3]);
        *(float4*)(cp + 4) = make_float4(o[4], o[5], o[6], o[7]);
    }
    __syncthreads();   // smem safe for next phase
}

// ---------------------------------------------------------------------------
// Attention body. Unit = (bh, 32-row i-group). Computes its own trig
// features from g_QK, then single-pass softmax (scores bounded |s|<=0.177)
// and o = softmax(s) @ V.
// score(i,j) = prod_{w=1..3}( cos(th_w)cos(q_iw) - sin(th_w)sin(q_iw)cos(k_jw) )
// ---------------------------------------------------------------------------
__device__ void attn_body(const float* __restrict__ ap, int bx, char* smu)
{
    const int ig = bx & 3;
    const int bh = bx >> 2;
    const int b = bh >> 3, h = bh & 7;

    float4* Vs   = (float4*)smu;             // [128][8] = 16KB
    float4* CKs  = (float4*)(smu + 16384);   // [128]    =  2KB
    float*  AB   = (float*) (smu + 18432);   // [32][6]
    float*  E    = (float*) (smu + 19200);   // [128][33]
    float*  Psum = (float*) (smu + 36096);   // [32][9]
    float*  Sinv = (float*) (smu + 37248);   // [32]

    const int tid = threadIdx.x;
    const float4* V4 = (const float4*)g_V;
#pragma unroll
    for (int t = 0; t < 4; t++) {
        const int idx = tid + (t << 8);
        const int j = idx >> 3, p = idx & 7;
        Vs[idx] = V4[(b*Sx + j)*64 + h*8 + p];
    }

    const float PI = 3.14159265358979323846f;
    if (tid < 128) {
        // k-side trig for row j
        const int j = tid;
        const float* r = &g_QK[(b*Sx + j)*64 + h*8 + 4];
        const float v0 = r[0], v1 = r[1], v2 = r[2], v3 = r[3];
        const float mn = fminf(fminf(v0, v1), fminf(v2, v3));
        const float mx = fmaxf(fmaxf(v0, v1), fmaxf(v2, v3));
        const float sc = PI / (mx - mn + 1e-8f);
        CKs[j] = make_float4(cosf((v1 - mn)*sc), cosf((v2 - mn)*sc),
                             cosf((v3 - mn)*sc), 0.f);
    } else if (tid < 160) {
        // q-side trig for row i
        const int il = tid - 128;
        const int i  = (ig << 5) + il;
        const float* r = &g_QK[(b*Sx + i)*64 + h*8];
        const float v0 = r[0], v1 = r[1], v2 = r[2], v3 = r[3];
        const float mn = fminf(fminf(v0, v1), fminf(v2, v3));
        const float mx = fmaxf(fmaxf(v0, v1), fmaxf(v2, v3));
        const float sc = PI / (mx - mn + 1e-8f);
        const float vv[3] = { v1, v2, v3 };
#pragma unroll
        for (int w = 0; w < 3; w++) {
            float sn, cs;
            sincosf((vv[w] - mn)*sc, &sn, &cs);
            const float th = ap[w + 1];
            AB[il*6 + w*2 + 0] = cosf(th) * cs;
            AB[il*6 + w*2 + 1] = sinf(th) * sn;
        }
    }
    __syncthreads();

    const int il = tid & 31;
    const int i  = (ig << 5) + il;

    // phase 1: exp scores, jg = tid>>5 handles 16 j's
    {
        const int jg = tid >> 5;
        const float A1 = AB[il*6+0], B1 = AB[il*6+1];
        const float A2 = AB[il*6+2], B2 = AB[il*6+3];
        const float A3 = AB[il*6+4], B3 = AB[il*6+5];
        const float SCALE = 0.17677669529663687f;   // 1/sqrt(32)
        float s = 0.f;
#pragma unroll
        for (int jj = 0; jj < 16; jj++) {
            const int j = (jg << 4) + jj;
            const float4 ck = CKs[j];
            const float sc = (A1 - B1*ck.x) * (A2 - B2*ck.y) * (A3 - B3*ck.z);
            const float e = __expf(sc * SCALE);
            E[j*33 + il] = e;
            s += e;
        }
        Psum[il*9 + jg] = s;
    }
    __syncthreads();
    if (tid < 32) {
        float s = 0.f;
#pragma unroll
        for (int jg = 0; jg < 8; jg++) s += Psum[tid*9 + jg];
        Sinv[tid] = 1.0f / s;
    }
    __syncthreads();

    // phase 2: p = tid>>5 owns one float4 dim-group (broadcast V loads)
    {
        const int p = tid >> 5;
        float4 o = make_float4(0.f, 0.f, 0.f, 0.f);
#pragma unroll 8
        for (int j = 0; j < 128; j++) {
            const float e = E[j*33 + il];
            const float4 v = Vs[(j << 3) + p];
            o.x = fmaf(e, v.x, o.x);
            o.y = fmaf(e, v.y, o.y);
            o.z = fmaf(e, v.z, o.z);
            o.w = fmaf(e, v.w, o.w);
        }
        const float inv = Sinv[il];
        o.x *= inv; o.y *= inv; o.z *= inv; o.w *= inv;
        ((float4*)g_AO)[(b*Sx + i)*64 + h*8 + p] = o;
    }
    __syncthreads();
}

// ---------------------------------------------------------------------------
// The single persistent kernel.
// Phase A: V-GEMM (blocks 0..127) + QK-GEMM (blocks 128..159)
// Phase B: attention (blocks 0..127)
// Phase C: O-GEMM (blocks 0..127)
// ---------------------------------------------------------------------------
__global__ void __launch_bounds__(256) uber_kernel(
    const float* __restrict__ x,
    const float* __restrict__ Wq, const float* __restrict__ bq,
    const float* __restrict__ Wk, const float* __restrict__ bk,
    const float* __restrict__ Wv, const float* __restrict__ bv,
    const float* __restrict__ Wo, const float* __restrict__ bo,
    const float* __restrict__ ap, float* __restrict__ out)
{
    __shared__ __align__(16) char smu[37504];
    __shared__ unsigned s_gen0;

    const int bx  = blockIdx.x;
    const int tid = threadIdx.x;
    if (tid == 0) s_gen0 = *(volatile unsigned*)&g_gen;
    __syncthreads();
    const unsigned gen0 = s_gen0;

    // ---- Phase A ----
    if (bx < 128) {
        gemm32x32((const float4*)x, (const float4*)Wv, nullptr, bv, nullptr,
                  g_V, (bx >> 3) << 5, (bx & 7) << 5, 256, 0, (float*)smu);
    } else {
        const int q = bx - 128;   // 32 tiles: 16 m-tiles x 2 n-tiles
        gemm32x32((const float4*)x, (const float4*)Wq, (const float4*)Wk, bq, bk,
                  g_QK, (q >> 1) << 5, (q & 1) << 5, 64, 1, (float*)smu);
    }
    grid_bar(gen0 + 1u);

    // ---- Phase B ----
    if (bx < 128) attn_body(ap, bx, smu);
    grid_bar(gen0 + 2u);

    // ---- Phase C ----
    if (bx < 128) {
        gemm32x32((const float4*)g_AO, (const float4*)Wo, nullptr, bo, nullptr,
                  out, (bx >> 3) << 5, (bx & 7) << 5, 256, 0, (float*)smu);
    }
}

// ---------------------------------------------------------------------------
extern "C" void kernel_launch(void* const* d_in, const int* in_sizes, int n_in,
                              void* d_out, int out_size)
{
    const float* x  = (const float*)d_in[0];
    const float* Wq = (const float*)d_in[1];
    const float* bq = (const float*)d_in[2];
    const float* Wk = (const float*)d_in[3];
    const float* bk = (const float*)d_in[4];
    const float* Wv = (const float*)d_in[5];
    const float* bv = (const float*)d_in[6];
    const float* Wo = (const float*)d_in[7];
    const float* bo = (const float*)d_in[8];
    const float* ap = (const float*)d_in[9];
    float* out = (float*)d_out;

    uber_kernel<<<NB, 256>>>(x, Wq, bq, Wk, bk, Wv, bv, Wo, bo, ap, out);
}

// round 9
// speedup vs baseline: 1.1780x; 1.1780x over previous
#include <cuda_runtime.h>
#include <math.h>
#include <stdint.h>

#define Bx 4
#define Sx 128
#define Dx 256
#define Hx 8

static __device__ float g_V [Bx*Sx*Dx];      // V = x@Wv.T + bv
static __device__ float g_QK[Bx*Sx*64];      // raw Q/K projections (8h x (4q|4k))
static __device__ float g_AO[Bx*Sx*Dx];      // attention output (pre-Wo)

// ---------------------------------------------------------------------------
// GEMM core (R5-proven inner loop + double-buffered K-chunks):
// C[m0+m][n0+n] = sum_k A[m][k]*B[n][k] + bias[n], K=256 (NT).
// 32m x 32n, 256 thr. Warp w: n-group ng=w&3 (8 n), k4-parity kp=w>>2.
// Thread: m=lane, 8 n, split accumulators. As/Bs [32][33] f4 padded.
// Chunk-1 LDGs issued before chunk-0 compute -> global latency hidden.
// qk mode: B rows / bias gathered from (Wq|Wk):
//   col -> h=col>>3, side=(col>>2)&1, w=col&3, row = h*32+w.
// ---------------------------------------------------------------------------
__device__ __forceinline__ void gemm32x32(
    const float4* __restrict__ A4,
    const float4* __restrict__ Bq4, const float4* __restrict__ Bk4,
    const float* __restrict__ biasq, const float* __restrict__ biask,
    float* __restrict__ C, int m0, int n0, int cstride, int qk, float* sm)
{
    float4* As = (float4*)sm;            // [32][33] float4
    float4* Bs = (float4*)sm + 32*33;    // [32][33] float4
    const int tid  = threadIdx.x;
    const int lane = tid & 31;
    const int w    = tid >> 5;
    const int ng   = w & 3;
    const int kp   = w >> 2;

    // per-thread staging coords (4 rows per thread, stride 8)
    const int r0 = tid >> 5;             // row base: r = r0 + t*8? No: idx pattern below
    (void)r0;

    float acc[8][2];
#pragma unroll
    for (int j = 0; j < 8; j++) { acc[j][0] = 0.f; acc[j][1] = 0.f; }

    const float4* Ap = As + lane*33 + kp;
    const float4* Bp = Bs + (ng*8)*33 + kp;

    // resolve this thread's 4 staging (row, col) pairs and B source rows once
    int srow[4], scol[4], brow[4];
    const float4* bsrc[4];
#pragma unroll
    for (int t = 0; t < 4; t++) {
        const int idx = tid + (t << 8);
        srow[t] = idx >> 5;
        scol[t] = idx & 31;
        if (qk) {
            const int col = n0 + srow[t];
            brow[t] = ((col >> 3)*32) + (col & 3);
            bsrc[t] = ((col >> 2) & 1) ? Bk4 : Bq4;
        } else {
            brow[t] = n0 + srow[t];
            bsrc[t] = Bq4;
        }
    }

    float4 ra[4], rb[4];
    // ---- prefetch chunk 0 into regs ----
#pragma unroll
    for (int t = 0; t < 4; t++) {
        ra[t] = A4[(m0 + srow[t])*64 + scol[t]];
        rb[t] = bsrc[t][brow[t]*64 + scol[t]];
    }
    // ---- stage chunk 0 ----
#pragma unroll
    for (int t = 0; t < 4; t++) {
        As[srow[t]*33 + scol[t]] = ra[t];
        Bs[srow[t]*33 + scol[t]] = rb[t];
    }
    __syncthreads();

    // ---- prefetch chunk 1 into regs (overlaps chunk-0 compute) ----
#pragma unroll
    for (int t = 0; t < 4; t++) {
        ra[t] = A4[(m0 + srow[t])*64 + 32 + scol[t]];
        rb[t] = bsrc[t][brow[t]*64 + 32 + scol[t]];
    }

    // ---- compute chunk 0 ----
#pragma unroll 4
    for (int k4 = 0; k4 < 16; k4++) {
        const float4 a = Ap[k4*2];
#pragma unroll
        for (int j = 0; j < 8; j++) {
            const float4 b = Bp[j*33 + k4*2];
            acc[j][0] = fmaf(a.x, b.x, acc[j][0]);
            acc[j][1] = fmaf(a.y, b.y, acc[j][1]);
            acc[j][0] = fmaf(a.z, b.z, acc[j][0]);
            acc[j][1] = fmaf(a.w, b.w, acc[j][1]);
        }
    }
    __syncthreads();

    // ---- stage chunk 1 ----
#pragma unroll
    for (int t = 0; t < 4; t++) {
        As[srow[t]*33 + scol[t]] = ra[t];
        Bs[srow[t]*33 + scol[t]] = rb[t];
    }
    __syncthreads();

    // ---- compute chunk 1 ----
#pragma unroll 4
    for (int k4 = 0; k4 < 16; k4++) {
        const float4 a = Ap[k4*2];
#pragma unroll
        for (int j = 0; j < 8; j++) {
            const float4 b = Bp[j*33 + k4*2];
            acc[j][0] = fmaf(a.x, b.x, acc[j][0]);
            acc[j][1] = fmaf(a.y, b.y, acc[j][1]);
            acc[j][0] = fmaf(a.z, b.z, acc[j][0]);
            acc[j][1] = fmaf(a.w, b.w, acc[j][1]);
        }
    }
    __syncthreads();

    // ---- cross-parity reduction through smem (17-pad: conflict-free) ----
    float* red = sm;
    if (kp == 1) {
#pragma unroll
        for (int j = 0; j < 8; j++) {
            red[(ng*32 + lane)*17 + j*2    ] = acc[j][0];
            red[(ng*32 + lane)*17 + j*2 + 1] = acc[j][1];
        }
    }
    __syncthreads();
    if (kp == 0) {
        const int n = n0 + ng*8;
        const float* rp = &red[(ng*32 + lane)*17];
        float o[8];
#pragma unroll
        for (int j = 0; j < 8; j++) {
            const int col = n + j;
            float bb;
            if (qk) {
                const int row = ((col >> 3)*32) + (col & 3);
                bb = (((col >> 2) & 1) ? biask : biasq)[row];
            } else {
                bb = biasq[col];
            }
            o[j] = acc[j][0] + acc[j][1] + rp[j*2] + rp[j*2 + 1] + bb;
        }
        float* cp = &C[(m0 + lane)*cstride + n];
        *(float4*)cp       = make_float4(o[0], o[1], o[2], o[3]);
        *(float4*)(cp + 4) = make_float4(o[4], o[5], o[6], o[7]);
    }
}

// ---------------------------------------------------------------------------
// Kernel 1: V-GEMM (blocks 0..127) + QK-GEMM (blocks 128..159)
// ---------------------------------------------------------------------------
__global__ void __launch_bounds__(256) k1_gemms(
    const float* __restrict__ x,
    const float* __restrict__ Wq, const float* __restrict__ bq,
    const float* __restrict__ Wk, const float* __restrict__ bk,
    const float* __restrict__ Wv, const float* __restrict__ bv)
{
    __shared__ float sm[8448];    // 33KB
    const int bx = blockIdx.x;
    if (bx < 128) {
        gemm32x32((const float4*)x, (const float4*)Wv, nullptr, bv, nullptr,
                  g_V, (bx >> 3) << 5, (bx & 7) << 5, 256, 0, sm);
    } else {
        const int q = bx - 128;   // 32 tiles: 16 m-tiles x 2 n-tiles
        gemm32x32((const float4*)x, (const float4*)Wq, (const float4*)Wk, bq, bk,
                  g_QK, (q >> 1) << 5, (q & 1) << 5, 64, 1, sm);
    }
}

// ---------------------------------------------------------------------------
// Kernel 2: attention with inline trig (verified in R8).
// 128 blocks = (bh, 32-row i-group), 256 threads.
// score(i,j) = prod_{w=1..3}( cos(th_w)cos(q_iw) - sin(th_w)sin(q_iw)cos(k_jw) )
// Scores bounded (|s|<=0.177) -> single-pass softmax.
// ---------------------------------------------------------------------------
__global__ void __launch_bounds__(256) attn_kernel(const float* __restrict__ ap)
{
    const int bx = blockIdx.x;
    const int ig = bx & 3;
    const int bh = bx >> 2;
    const int b = bh >> 3, h = bh & 7;

    __shared__ float4 Vs[1024];      // [j][p]
    __shared__ float4 CKs[128];
    __shared__ float  AB[32*6];
    __shared__ float  E[128*33];     // [j][il], pad 33
    __shared__ float  Psum[32*9];
    __shared__ float  Sinv[32];

    const int tid = threadIdx.x;
    const float4* V4 = (const float4*)g_V;
#pragma unroll
    for (int t = 0; t < 4; t++) {
        const int idx = tid + (t << 8);
        const int j = idx >> 3, p = idx & 7;
        Vs[idx] = V4[(b*Sx + j)*64 + h*8 + p];
    }

    const float PI = 3.14159265358979323846f;
    if (tid < 128) {
        const int j = tid;
        const float* r = &g_QK[(b*Sx + j)*64 + h*8 + 4];
        const float v0 = r[0], v1 = r[1], v2 = r[2], v3 = r[3];
        const float mn = fminf(fminf(v0, v1), fminf(v2, v3));
        const float mx = fmaxf(fmaxf(v0, v1), fmaxf(v2, v3));
        const float sc = PI / (mx - mn + 1e-8f);
        CKs[j] = make_float4(cosf((v1 - mn)*sc), cosf((v2 - mn)*sc),
                             cosf((v3 - mn)*sc), 0.f);
    } else if (tid < 160) {
        const int il = tid - 128;
        const int i  = (ig << 5) + il;
        const float* r = &g_QK[(b*Sx + i)*64 + h*8];
        const float v0 = r[0], v1 = r[1], v2 = r[2], v3 = r[3];
        const float mn = fminf(fminf(v0, v1), fminf(v2, v3));
        const float mx = fmaxf(fmaxf(v0, v1), fmaxf(v2, v3));
        const float sc = PI / (mx - mn + 1e-8f);
        const float vv[3] = { v1, v2, v3 };
#pragma unroll
        for (int w = 0; w < 3; w++) {
            float sn, cs;
            sincosf((vv[w] - mn)*sc, &sn, &cs);
            const float th = ap[w + 1];
            AB[il*6 + w*2 + 0] = cosf(th) * cs;
            AB[il*6 + w*2 + 1] = sinf(th) * sn;
        }
    }
    __syncthreads();

    const int il = tid & 31;
    const int i  = (ig << 5) + il;

    {
        const int jg = tid >> 5;
        const float A1 = AB[il*6+0], B1 = AB[il*6+1];
        const float A2 = AB[il*6+2], B2 = AB[il*6+3];
        const float A3 = AB[il*6+4], B3 = AB[il*6+5];
        const float SCALE = 0.17677669529663687f;   // 1/sqrt(32)
        float s = 0.f;
#pragma unroll
        for (int jj = 0; jj < 16; jj++) {
            const int j = (jg << 4) + jj;
            const float4 ck = CKs[j];
            const float sc = (A1 - B1*ck.x) * (A2 - B2*ck.y) * (A3 - B3*ck.z);
            const float e = __expf(sc * SCALE);
            E[j*33 + il] = e;
            s += e;
        }
        Psum[il*9 + jg] = s;
    }
    __syncthreads();
    if (tid < 32) {
        float s = 0.f;
#pragma unroll
        for (int jg = 0; jg < 8; jg++) s += Psum[tid*9 + jg];
        Sinv[tid] = 1.0f / s;
    }
    __syncthreads();

    {
        const int p = tid >> 5;
        float4 o = make_float4(0.f, 0.f, 0.f, 0.f);
#pragma unroll 8
        for (int j = 0; j < 128; j++) {
            const float e = E[j*33 + il];
            const float4 v = Vs[(j << 3) + p];
            o.x = fmaf(e, v.x, o.x);
            o.y = fmaf(e, v.y, o.y);
            o.z = fmaf(e, v.z, o.z);
            o.w = fmaf(e, v.w, o.w);
        }
        const float inv = Sinv[il];
        o.x *= inv; o.y *= inv; o.z *= inv; o.w *= inv;
        ((float4*)g_AO)[(b*Sx + i)*64 + h*8 + p] = o;
    }
}

// ---------------------------------------------------------------------------
// Kernel 3: out = g_AO @ Wo.T + bo  (128 blocks)
// ---------------------------------------------------------------------------
__global__ void __launch_bounds__(256) k3_ogemm(
    const float* __restrict__ Wo, const float* __restrict__ bo,
    float* __restrict__ out)
{
    __shared__ float sm[8448];
    const int bx = blockIdx.x;
    gemm32x32((const float4*)g_AO, (const float4*)Wo, nullptr, bo, nullptr,
              out, (bx >> 3) << 5, (bx & 7) << 5, 256, 0, sm);
}

// ---------------------------------------------------------------------------
extern "C" void kernel_launch(void* const* d_in, const int* in_sizes, int n_in,
                              void* d_out, int out_size)
{
    const float* x  = (const float*)d_in[0];
    const float* Wq = (const float*)d_in[1];
    const float* bq = (const float*)d_in[2];
    const float* Wk = (const float*)d_in[3];
    const float* bk = (const float*)d_in[4];
    const float* Wv = (const float*)d_in[5];
    const float* bv = (const float*)d_in[6];
    const float* Wo = (const float*)d_in[7];
    const float* bo = (const float*)d_in[8];
    const float* ap = (const float*)d_in[9];
    float* out = (float*)d_out;

    k1_gemms<<<160, 256>>>(x, Wq, bq, Wk, bk, Wv, bv);
    attn_kernel<<<128, 256>>>(ap);
    k3_ogemm<<<128, 256>>>(Wo, bo, out);
}